// round 10
// baseline (speedup 1.0000x reference)
#include <cuda_runtime.h>
#include <cstdint>
#include <cstddef>

// VectorQuantizer on GB300 (sm_103a)
// int8 dp4a scoring (exact int32 accumulation, quantization error only)
// + margin flag + exact fp32 rescore of flagged pixels (proven k_fix).
// z_e: (16,256,64,64) fp32 ; embedding: (1024,256) fp32

#define NEMB 1024
#define EDIM 256
#define HW   4096
#define NPIX 65536
#define NC   16777216

#define MARGIN  4.5f
#define FLAGCAP 65536

// smem layout for k_argmin_i8
#define SM_A    0          // A[64 slots][128 pix] u32 = 32KB (staged once)
#define SM_B    32768      // 3 stages x 16 slots x 128 codes u32 = 24KB
#define SM_SE2  57344      // 1024 f
#define SM_SSE  61440      // 1024 f
#define SM_SSX  65536      // 128 f
#define SM_TOT  66048

// ---- device scratch ----
__device__ __align__(128) uint32_t g_QxT[64 * 65536];  // [kslot][pix] 4 packed int8
__device__ __align__(128) uint32_t g_QeT[64 * 1024];   // [kslot][code]
__device__ __align__(16) float g_sx[NPIX];             // per-pixel scale (max/127)
__device__ __align__(16) float g_se[NEMB];             // per-code scale
__device__ __align__(16) float g_e2[NEMB];             // exact fp32 norms
__device__ int    g_idx[NPIX];
__device__ double g_part[2048];
__device__ int    g_nflag;
__device__ int    g_flag[FLAGCAP];

static __device__ __forceinline__ uint32_t s2u(const void* p) {
    uint32_t a;
    asm("{ .reg .u64 t; cvta.to.shared.u64 t, %1; cvt.u32.u64 %0, t; }" : "=r"(a) : "l"(p));
    return a;
}
static __device__ __forceinline__ void cpa16(uint32_t dst, const void* src) {
    asm volatile("cp.async.cg.shared.global [%0], [%1], 16;" :: "r"(dst), "l"(src));
}
static __device__ __forceinline__ uint32_t pack4(float x0, float x1, float x2, float x3,
                                                 float inv) {
    int q0 = __float2int_rn(x0 * inv);
    int q1 = __float2int_rn(x1 * inv);
    int q2 = __float2int_rn(x2 * inv);
    int q3 = __float2int_rn(x3 * inv);
    return (uint32_t)(q0 & 0xFF) | ((uint32_t)(q1 & 0xFF) << 8) |
           ((uint32_t)(q2 & 0xFF) << 16) | ((uint32_t)(q3 & 0xFF) << 24);
}

// ============================================================
// K1: embedding -> packed int8 (per-code scale) + exact norms.
// One warp per code.
// ============================================================
__global__ __launch_bounds__(256) void k_prep_e(const float* __restrict__ emb) {
    int warp = (blockIdx.x * blockDim.x + threadIdx.x) >> 5;
    int lane = threadIdx.x & 31;
    if (warp >= NEMB) return;
    const float* row = emb + (size_t)warp * EDIM;
    int k0 = lane << 3;
    float4 v0 = *reinterpret_cast<const float4*>(row + k0);
    float4 v1 = *reinterpret_cast<const float4*>(row + k0 + 4);
    float xs[8] = {v0.x, v0.y, v0.z, v0.w, v1.x, v1.y, v1.z, v1.w};
    float s = 0.f, m = 0.f;
    #pragma unroll
    for (int j = 0; j < 8; ++j) {
        s += xs[j] * xs[j];
        m = fmaxf(m, fabsf(xs[j]));
    }
    #pragma unroll
    for (int o = 16; o; o >>= 1) {
        s += __shfl_xor_sync(0xFFFFFFFFu, s, o);
        m = fmaxf(m, __shfl_xor_sync(0xFFFFFFFFu, m, o));
    }
    float inv = (m > 0.f) ? 127.f / m : 0.f;
    if (lane == 0) {
        g_e2[warp] = s;
        g_se[warp] = m * (1.f / 127.f);
    }
    g_QeT[(size_t)(lane * 2)     * NEMB + warp] = pack4(xs[0], xs[1], xs[2], xs[3], inv);
    g_QeT[(size_t)(lane * 2 + 1) * NEMB + warp] = pack4(xs[4], xs[5], xs[6], xs[7], inv);
}

// ============================================================
// K2: z_e -> packed int8 transposed [kslot][pix] + per-pixel scale.
// ============================================================
__global__ __launch_bounds__(256) void k_prep_x(const float* __restrict__ z) {
    __shared__ float sz[32][257];
    __shared__ float smax[8][32];
    __shared__ float sinv[32];
    const int t = threadIdx.x;
    const int pix0 = blockIdx.x << 5;
    const float* zb = z + (((size_t)(pix0 >> 12)) << 20) + (pix0 & 4095);

    if (blockIdx.x == 0 && t == 0) g_nflag = 0;

    #pragma unroll 8
    for (int it = 0; it < 32; ++it) {
        int slot = t + (it << 8);
        int k = slot >> 5, p = slot & 31;
        sz[p][k] = zb[(size_t)k * HW + p];
    }
    __syncthreads();

    {
        int p = t & 31, ch = t >> 5;
        float m = 0.f;
        #pragma unroll 8
        for (int k = ch * 32; k < ch * 32 + 32; ++k) m = fmaxf(m, fabsf(sz[p][k]));
        smax[ch][p] = m;
    }
    __syncthreads();
    if (t < 32) {
        float m = smax[0][t];
        #pragma unroll
        for (int c = 1; c < 8; ++c) m = fmaxf(m, smax[c][t]);
        g_sx[pix0 + t] = m * (1.f / 127.f);
        sinv[t] = (m > 0.f) ? 127.f / m : 0.f;
    }
    __syncthreads();

    #pragma unroll
    for (int it = 0; it < 8; ++it) {
        int item = t + (it << 8);       // 0..2047
        int p = item & 31, s = item >> 5;
        float inv = sinv[p];
        g_QxT[(size_t)s * NPIX + pix0 + p] =
            pack4(sz[p][s * 4], sz[p][s * 4 + 1], sz[p][s * 4 + 2], sz[p][s * 4 + 3], inv);
    }
}

// ============================================================
// K3: dp4a scoring + fused argmin with margin flag.
// CTA = 128 pixels x 1024 codes. A (64 slots x 128 pix, 32KB) staged once;
// B streamed in 32 steps (8 cc x 4 kc, 16 slots x 128 codes = 8KB each),
// 3-stage cp.async (R9-proven wait->sync->issue). Thread tile 8 pix x 8 codes.
// ============================================================
__global__ __launch_bounds__(256, 2) void k_argmin_i8() {
    extern __shared__ char smem[];
    const uint32_t sbase = s2u(smem);
    float* se2p = reinterpret_cast<float*>(smem + SM_SE2);
    float* ssep = reinterpret_cast<float*>(smem + SM_SSE);
    float* ssxp = reinterpret_cast<float*>(smem + SM_SSX);

    const int t  = threadIdx.x;
    const int tx = t & 15;             // 8 codes  (tx*8..+7)
    const int ty = t >> 4;             // 8 pixels (ty*8..+7)
    const int pix0 = blockIdx.x << 7;

    // ---- prologue: A (group 0, with B step 0) + B step 1 ----
    #pragma unroll
    for (int i = 0; i < 8; ++i) {
        int g = t + (i << 8);
        int r = g >> 5, c = g & 31;
        cpa16(sbase + r * 512 + (c << 4), &g_QxT[(size_t)r * NPIX + pix0 + (c << 2)]);
    }
    #pragma unroll
    for (int i = 0; i < 2; ++i) {
        int g = t + (i << 8);
        int r = g >> 5, c = g & 31;
        cpa16(sbase + SM_B + r * 512 + (c << 4), &g_QeT[(size_t)r * NEMB + (c << 2)]);
    }
    asm volatile("cp.async.commit_group;" ::: "memory");
    #pragma unroll
    for (int i = 0; i < 2; ++i) {
        int g = t + (i << 8);
        int r = g >> 5, c = g & 31;
        cpa16(sbase + SM_B + 8192 + r * 512 + (c << 4),
              &g_QeT[(size_t)(16 + r) * NEMB + (c << 2)]);
    }
    asm volatile("cp.async.commit_group;" ::: "memory");

    // scalar tables
    #pragma unroll
    for (int i = 0; i < 4; ++i) {
        se2p[t + (i << 8)] = g_e2[t + (i << 8)];
        ssep[t + (i << 8)] = g_se[t + (i << 8)];
    }
    if (t < 128) ssxp[t] = g_sx[pix0 + t];

    float bv[8], b2[8];
    int   bi[8];
    #pragma unroll
    for (int i = 0; i < 8; ++i) { bv[i] = 3.402823466e38f; b2[i] = 3.402823466e38f; bi[i] = 0; }

    int acc[8][8];

    #pragma unroll 1
    for (int g = 0; g < 32; ++g) {
        if (g < 31) {
            asm volatile("cp.async.wait_group 1;" ::: "memory");
        } else {
            asm volatile("cp.async.wait_group 0;" ::: "memory");
        }
        __syncthreads();

        if (g + 2 < 32) {
            const int g2 = g + 2;
            const int cc2 = g2 >> 2, kc2 = g2 & 3;
            #pragma unroll
            for (int i = 0; i < 2; ++i) {
                int gg = t + (i << 8);
                int r = gg >> 5, c = gg & 31;
                cpa16(sbase + SM_B + (g2 % 3) * 8192 + r * 512 + (c << 4),
                      &g_QeT[(size_t)(kc2 * 16 + r) * NEMB + cc2 * 128 + (c << 2)]);
            }
            asm volatile("cp.async.commit_group;" ::: "memory");
        }

        const int cc = g >> 2, kc = g & 3;
        if (kc == 0) {
            #pragma unroll
            for (int i = 0; i < 8; ++i)
                #pragma unroll
                for (int j = 0; j < 8; ++j) acc[i][j] = 0;
        }

        const char* pA = smem + kc * 8192;              // slots kc*16..+15
        const char* pB = smem + SM_B + (g % 3) * 8192;

        #pragma unroll 2
        for (int s = 0; s < 16; ++s) {
            uint4 a01 = *reinterpret_cast<const uint4*>(pA + s * 512 + (ty << 5));
            uint4 a23 = *reinterpret_cast<const uint4*>(pA + s * 512 + (ty << 5) + 16);
            uint4 b01 = *reinterpret_cast<const uint4*>(pB + s * 512 + (tx << 5));
            uint4 b23 = *reinterpret_cast<const uint4*>(pB + s * 512 + (tx << 5) + 16);
            int av[8] = {(int)a01.x, (int)a01.y, (int)a01.z, (int)a01.w,
                         (int)a23.x, (int)a23.y, (int)a23.z, (int)a23.w};
            int bw[8] = {(int)b01.x, (int)b01.y, (int)b01.z, (int)b01.w,
                         (int)b23.x, (int)b23.y, (int)b23.z, (int)b23.w};
            #pragma unroll
            for (int i = 0; i < 8; ++i)
                #pragma unroll
                for (int j = 0; j < 8; ++j)
                    acc[i][j] = __dp4a(av[i], bw[j], acc[i][j]);
        }

        // ---- epilogue at end of each 128-code chunk ----
        if (kc == 3) {
            #pragma unroll
            for (int i = 0; i < 8; ++i) {
                float fx = -2.f * ssxp[(ty << 3) + i];
                #pragma unroll
                for (int j = 0; j < 8; ++j) {
                    int c = (cc << 7) + (tx << 3) + j;
                    float sc = fmaf(fx * ssep[c], (float)acc[i][j], se2p[c]);
                    if (sc < bv[i]) { b2[i] = bv[i]; bv[i] = sc; bi[i] = c; }
                    else if (sc < b2[i]) b2[i] = sc;
                }
            }
        }
    }

    // ---- cross-thread merge over 16 tx lanes (keep best + 2nd) ----
    #pragma unroll
    for (int o = 8; o; o >>= 1) {
        #pragma unroll
        for (int i = 0; i < 8; ++i) {
            float ov = __shfl_xor_sync(0xFFFFFFFFu, bv[i], o);
            float o2 = __shfl_xor_sync(0xFFFFFFFFu, b2[i], o);
            int   oi = __shfl_xor_sync(0xFFFFFFFFu, bi[i], o);
            if (ov < bv[i] || (ov == bv[i] && oi < bi[i])) {
                b2[i] = fminf(bv[i], o2);
                bv[i] = ov; bi[i] = oi;
            } else {
                b2[i] = fminf(b2[i], ov);
            }
        }
    }
    if (tx == 0) {
        #pragma unroll
        for (int i = 0; i < 8; ++i) {
            int prow = pix0 + (ty << 3) + i;
            g_idx[prow] = bi[i];
            if (b2[i] - bv[i] < MARGIN) {
                int pos = atomicAdd(&g_nflag, 1);
                if (pos < FLAGCAP) g_flag[pos] = prow;
            }
        }
    }
}

// ============================================================
// K4: exact fp32 rescore of margin-flagged pixels (one warp each, proven)
// ============================================================
__global__ __launch_bounds__(256) void k_fix(const float* __restrict__ z,
                                             const float* __restrict__ emb) {
    __shared__ float sx[8][256];
    const int w = threadIdx.x >> 5, lane = threadIdx.x & 31;
    int n = g_nflag; if (n > FLAGCAP) n = FLAGCAP;
    for (int f = blockIdx.x * 8 + w; f < n; f += gridDim.x * 8) {
        int pix = g_flag[f];
        const float* zb = z + (((size_t)(pix >> 12)) << 20) + (pix & 4095);
        for (int k = lane; k < EDIM; k += 32) sx[w][k] = zb[(size_t)k * HW];
        __syncwarp();
        float bv = 3.402823466e38f; int bi = 0;
        for (int c = lane; c < NEMB; c += 32) {
            const float* e = emb + (size_t)c * EDIM;
            float a0 = 0.f, a1 = 0.f, a2 = 0.f, a3 = 0.f;
            #pragma unroll 8
            for (int k = 0; k < EDIM; k += 4) {
                a0 = fmaf(sx[w][k],     e[k],     a0);
                a1 = fmaf(sx[w][k + 1], e[k + 1], a1);
                a2 = fmaf(sx[w][k + 2], e[k + 2], a2);
                a3 = fmaf(sx[w][k + 3], e[k + 3], a3);
            }
            float sc = g_e2[c] - 2.f * ((a0 + a1) + (a2 + a3));
            if (sc < bv) { bv = sc; bi = c; }
        }
        #pragma unroll
        for (int o = 16; o; o >>= 1) {
            float ov = __shfl_xor_sync(0xFFFFFFFFu, bv, o);
            int   oi = __shfl_xor_sync(0xFFFFFFFFu, bi, o);
            if (ov < bv || (ov == bv && oi < bi)) { bv = ov; bi = oi; }
        }
        if (lane == 0) g_idx[pix] = bi;
        __syncwarp();
    }
}

// ============================================================
// K5: gather z_q, write z_q_st = z_e + (z_q - z_e), loss partials
// ============================================================
__global__ __launch_bounds__(256)
void k_gather(const float* __restrict__ z, const float* __restrict__ emb,
              float* __restrict__ out) {
    __shared__ float sE[32 * 260];
    __shared__ float swarp[8];
    const int t = threadIdx.x;
    const int pix0 = blockIdx.x << 5;

    #pragma unroll
    for (int it = 0; it < 8; ++it) {
        int slot = t + (it << 8);
        int p = slot >> 6, c4 = slot & 63;
        int idx = g_idx[pix0 + p];
        float4 v = *reinterpret_cast<const float4*>(emb + (size_t)idx * EDIM + (c4 << 2));
        *reinterpret_cast<float4*>(&sE[p * 260 + (c4 << 2)]) = v;
    }
    __syncthreads();

    const float* zb = z   + (((size_t)(pix0 >> 12)) << 20) + (pix0 & 4095);
    float*       ob = out + (((size_t)(pix0 >> 12)) << 20) + (pix0 & 4095);

    float lsum = 0.f;
    #pragma unroll
    for (int it = 0; it < 8; ++it) {
        int slot = t + (it << 8);
        int hw = slot & 31, c4 = slot >> 5;
        float4 e = *reinterpret_cast<const float4*>(&sE[hw * 260 + (c4 << 2)]);
        float ev[4] = {e.x, e.y, e.z, e.w};
        #pragma unroll
        for (int j = 0; j < 4; ++j) {
            size_t gg = (size_t)((c4 << 2) + j) * HW + hw;
            float ze = zb[gg];
            float d = ev[j] - ze;
            ob[gg] = ze + d;
            lsum += d * d;
        }
    }
    #pragma unroll
    for (int o = 16; o; o >>= 1) lsum += __shfl_xor_sync(0xFFFFFFFFu, lsum, o);
    if ((t & 31) == 0) swarp[t >> 5] = lsum;
    __syncthreads();
    if (t == 0) {
        double s = 0.0;
        #pragma unroll
        for (int w = 0; w < 8; ++w) s += (double)swarp[w];
        g_part[blockIdx.x] = s;
    }
}

// ============================================================
// K6: loss finalize
// ============================================================
__global__ void k_loss(float* __restrict__ out, int out_size) {
    __shared__ double sd[256];
    int t = threadIdx.x;
    double s = 0.0;
    for (int i = t; i < 2048; i += 256) s += g_part[i];
    sd[t] = s;
    __syncthreads();
    for (int o = 128; o; o >>= 1) {
        if (t < o) sd[t] += sd[t + o];
        __syncthreads();
    }
    if (t == 0 && out_size > NC)
        out[NC] = (float)(0.25 * sd[0] / (double)NC);
}

// ============================================================
extern "C" void kernel_launch(void* const* d_in, const int* in_sizes, int n_in,
                              void* d_out, int out_size) {
    const float* z   = (const float*)d_in[0];
    const float* emb = (const float*)d_in[1];
    float* out = (float*)d_out;

    cudaFuncSetAttribute(k_argmin_i8, cudaFuncAttributeMaxDynamicSharedMemorySize, SM_TOT);

    k_prep_e   <<<128,  256>>>(emb);
    k_prep_x   <<<2048, 256>>>(z);
    k_argmin_i8<<<512,  256, SM_TOT>>>();
    k_fix      <<<256,  256>>>(z, emb);
    k_gather   <<<2048, 256>>>(z, emb, out);
    k_loss     <<<1,    256>>>(out, out_size);
}